// round 9
// baseline (speedup 1.0000x reference)
#include <cuda_runtime.h>
#include <cuda_bf16.h>
#include <cstdint>

// ---------------------------------------------------------------------------
// Problem constants
// ---------------------------------------------------------------------------
#define LAYERS 4
#define HDIM   512
#define NHEAD  8
#define DHQK   32
#define DHV    64
#define QKDIM  (NHEAD * DHQK)   // 256
#define VDIM   (NHEAD * DHV)    // 512
#define FDIM   1408
#define NTOK   2048              // B*P = 8*256
#define CAPV   15.0f
#define EPSV   1e-6f

// ---------------------------------------------------------------------------
// Device scratch (static: no allocation allowed)
// ---------------------------------------------------------------------------
__device__ float g_x   [NTOK * HDIM];
__device__ float g_q   [NTOK * QKDIM];
__device__ float g_k   [NTOK * QKDIM];
__device__ float g_v   [NTOK * VDIM];
__device__ float g_og  [NTOK * VDIM];
__device__ float g_if  [NTOK * 64];
__device__ float g_gate[NTOK * FDIM];
__device__ float g_up  [NTOK * FDIM];

// hi/lo split activations (GEMM A-operands)
__device__ float g_xn_h [NTOK * HDIM];
__device__ float g_xn_l [NTOK * HDIM];
__device__ float g_hv_h [NTOK * VDIM];
__device__ float g_hv_l [NTOK * VDIM];
__device__ float g_act_h[NTOK * FDIM];
__device__ float g_act_l[NTOK * FDIM];

// hi/lo split weights (GEMM B-operands)
__device__ float w_q_h [LAYERS * HDIM * QKDIM];
__device__ float w_q_l [LAYERS * HDIM * QKDIM];
__device__ float w_k_h [LAYERS * HDIM * QKDIM];
__device__ float w_k_l [LAYERS * HDIM * QKDIM];
__device__ float w_v_h [LAYERS * HDIM * VDIM];
__device__ float w_v_l [LAYERS * HDIM * VDIM];
__device__ float w_og_h[LAYERS * HDIM * VDIM];
__device__ float w_og_l[LAYERS * HDIM * VDIM];
__device__ float w_o_h [LAYERS * VDIM * HDIM];
__device__ float w_o_l [LAYERS * VDIM * HDIM];
__device__ float w_g_h [LAYERS * HDIM * FDIM];
__device__ float w_g_l [LAYERS * HDIM * FDIM];
__device__ float w_u_h [LAYERS * HDIM * FDIM];
__device__ float w_u_l [LAYERS * HDIM * FDIM];
__device__ float w_d_h [LAYERS * FDIM * HDIM];
__device__ float w_d_l [LAYERS * FDIM * HDIM];
__device__ float w_if_h[LAYERS * HDIM * 64];
__device__ float w_if_l[LAYERS * HDIM * 64];

// ---------------------------------------------------------------------------
// Helpers
// ---------------------------------------------------------------------------
__device__ __forceinline__ float to_tf32(float x) {
    uint32_t u;
    asm("cvt.rna.tf32.f32 %0, %1;" : "=r"(u) : "f"(x));
    return __uint_as_float(u);
}

__device__ __forceinline__ float softcapf(float x) {
    return CAPV * tanhf(x * (1.0f / CAPV));
}

__device__ __forceinline__ float logsigf(float x) {
    return (x >= 0.0f) ? -log1pf(expf(-x)) : (x - log1pf(expf(x)));
}

__device__ __forceinline__ float sigmoidf_(float x) {
    return 1.0f / (1.0f + expf(-x));
}

__device__ __forceinline__ void cpasync16(uint32_t dst, const void* src) {
    asm volatile("cp.async.cg.shared.global [%0], [%1], 16;\n"
                 :: "r"(dst), "l"(src));
}

#define MMA_TF32(acc, a0, a1, a2, a3, b0, b1)                                  \
    asm volatile(                                                              \
        "mma.sync.aligned.m16n8k8.row.col.f32.tf32.tf32.f32 "                  \
        "{%0,%1,%2,%3}, {%4,%5,%6,%7}, {%8,%9}, {%0,%1,%2,%3};\n"              \
        : "+f"(acc[0]), "+f"(acc[1]), "+f"(acc[2]), "+f"(acc[3])               \
        : "r"(a0), "r"(a1), "r"(a2), "r"(a3), "r"(b0), "r"(b1))

// ---------------------------------------------------------------------------
// Split fp32 -> (hi = tf32(v), lo = tf32(v - hi))  vectorized; n4 = n/4
// ---------------------------------------------------------------------------
__global__ __launch_bounds__(256) void split_tf32_kernel(
    const float* __restrict__ in, float* __restrict__ hi,
    float* __restrict__ lo, int n4)
{
    int i = blockIdx.x * blockDim.x + threadIdx.x;
    if (i >= n4) return;
    float4 v = reinterpret_cast<const float4*>(in)[i];
    float4 h, l;
    h.x = to_tf32(v.x); l.x = to_tf32(v.x - h.x);
    h.y = to_tf32(v.y); l.y = to_tf32(v.y - h.y);
    h.z = to_tf32(v.z); l.z = to_tf32(v.z - h.z);
    h.w = to_tf32(v.w); l.w = to_tf32(v.w - h.w);
    reinterpret_cast<float4*>(hi)[i] = h;
    reinterpret_cast<float4*>(lo)[i] = l;
}

// ---------------------------------------------------------------------------
// Multi-segment 3xTF32 GEMM with PRE-SPLIT operands (no cvt in the k-loop).
// C_s = A @ B_s (+ Res_s); A given as (Ahi,Alo), each B as (Bhi,Blo).
// acc += ah*bl + al*bh + ah*bh  — bit-identical to in-kernel splitting.
// CTA 64x64x16, 128 threads (4 warps 2x2), 2-stage cp.async.
// ---------------------------------------------------------------------------
#define MAXSEG 5
struct GemmSeg {
    const float* Bh;
    const float* Bl;
    float*       C;
    const float* Res;   // nullptr = no residual add
    int          N;
    int          nstart;
};
struct GemmDesc {
    int nseg;
    GemmSeg seg[MAXSEG];
};

#define BM 64
#define BN 64
#define BK 16
#define BKP 20   // 80B rows (16B multiple); banks (20g+t)%32 distinct -> conflict-free
#define BNP 72   // 288B rows; banks (8t+g)%32 distinct -> conflict-free

__global__ __launch_bounds__(128) void gemm_presplit_kernel(
    const float* __restrict__ Ahi, const float* __restrict__ Alo,
    int M, int K, GemmDesc d)
{
    __shared__ float Ah[2][BM][BKP];   // 10240 B
    __shared__ float Al[2][BM][BKP];   // 10240 B
    __shared__ float Bh[2][BK][BNP];   //  9216 B
    __shared__ float Bl[2][BK][BNP];   //  9216 B   => 38912 B total

    // --- segment lookup (uniform per CTA) ---
    const int nblk = blockIdx.x;
    int si = 0;
#pragma unroll
    for (int t = 1; t < MAXSEG; ++t)
        if (t < d.nseg && nblk >= d.seg[t].nstart) si = t;
    const float* __restrict__ SBh = d.seg[si].Bh;
    const float* __restrict__ SBl = d.seg[si].Bl;
    float*       __restrict__ C   = d.seg[si].C;
    const float* __restrict__ Res = d.seg[si].Res;
    const int N  = d.seg[si].N;
    const int n0 = (nblk - d.seg[si].nstart) * BN;
    const int m0 = blockIdx.y * BM;

    const int tid  = threadIdx.x;
    const int warp = tid >> 5;
    const int lane = tid & 31;
    const int wm   = (warp >> 1) * 32;
    const int wn   = (warp & 1) * 32;
    const int gid  = lane >> 2;          // 0..7
    const int tig  = lane & 3;           // 0..3

    // per-thread tile-load coords: A tile 64x16 = 256 16B-chunks, 2/thread/dtype
    //                              B tile 16x64 = 256 16B-chunks, 2/thread/dtype
    int a_r[2], a_c[2], b_r[2], b_c[2];
    uint32_t ah_dst[2][2], al_dst[2][2], bh_dst[2][2], bl_dst[2][2];
#pragma unroll
    for (int it = 0; it < 2; ++it) {
        int idx = tid + it * 128;
        a_r[it] = idx >> 2;        a_c[it] = (idx & 3) * 4;
        b_r[it] = idx >> 4;        b_c[it] = (idx & 15) * 4;
#pragma unroll
        for (int s = 0; s < 2; ++s) {
            ah_dst[s][it] = (uint32_t)__cvta_generic_to_shared(&Ah[s][a_r[it]][a_c[it]]);
            al_dst[s][it] = (uint32_t)__cvta_generic_to_shared(&Al[s][a_r[it]][a_c[it]]);
            bh_dst[s][it] = (uint32_t)__cvta_generic_to_shared(&Bh[s][b_r[it]][b_c[it]]);
            bl_dst[s][it] = (uint32_t)__cvta_generic_to_shared(&Bl[s][b_r[it]][b_c[it]]);
        }
    }

    float acc[2][4][4];
#pragma unroll
    for (int mt = 0; mt < 2; ++mt)
#pragma unroll
        for (int nt = 0; nt < 4; ++nt)
#pragma unroll
            for (int r = 0; r < 4; ++r) acc[mt][nt][r] = 0.0f;

    const int nk = K / BK;

#pragma unroll
    for (int it = 0; it < 2; ++it) {
        cpasync16(ah_dst[0][it], Ahi + (size_t)(m0 + a_r[it]) * K + a_c[it]);
        cpasync16(al_dst[0][it], Alo + (size_t)(m0 + a_r[it]) * K + a_c[it]);
        cpasync16(bh_dst[0][it], SBh + (size_t)b_r[it] * N + n0 + b_c[it]);
        cpasync16(bl_dst[0][it], SBl + (size_t)b_r[it] * N + n0 + b_c[it]);
    }
    asm volatile("cp.async.commit_group;\n");

    for (int kt = 0; kt < nk; ++kt) {
        const int cur = kt & 1;
        if (kt + 1 < nk) {
            const int nxt = cur ^ 1;
            const int koff = (kt + 1) * BK;
#pragma unroll
            for (int it = 0; it < 2; ++it) {
                cpasync16(ah_dst[nxt][it], Ahi + (size_t)(m0 + a_r[it]) * K + koff + a_c[it]);
                cpasync16(al_dst[nxt][it], Alo + (size_t)(m0 + a_r[it]) * K + koff + a_c[it]);
                cpasync16(bh_dst[nxt][it], SBh + (size_t)(koff + b_r[it]) * N + n0 + b_c[it]);
                cpasync16(bl_dst[nxt][it], SBl + (size_t)(koff + b_r[it]) * N + n0 + b_c[it]);
            }
            asm volatile("cp.async.commit_group;\n");
            asm volatile("cp.async.wait_group 1;\n");
        } else {
            asm volatile("cp.async.wait_group 0;\n");
        }
        __syncthreads();

#pragma unroll
        for (int kk = 0; kk < BK; kk += 8) {
            uint32_t ah[2][4], al[2][4], bh_[4][2], bl_[4][2];
#pragma unroll
            for (int mt = 0; mt < 2; ++mt) {
                int r = wm + mt * 16 + gid;
                ah[mt][0] = __float_as_uint(Ah[cur][r    ][kk + tig]);
                ah[mt][1] = __float_as_uint(Ah[cur][r + 8][kk + tig]);
                ah[mt][2] = __float_as_uint(Ah[cur][r    ][kk + tig + 4]);
                ah[mt][3] = __float_as_uint(Ah[cur][r + 8][kk + tig + 4]);
                al[mt][0] = __float_as_uint(Al[cur][r    ][kk + tig]);
                al[mt][1] = __float_as_uint(Al[cur][r + 8][kk + tig]);
                al[mt][2] = __float_as_uint(Al[cur][r    ][kk + tig + 4]);
                al[mt][3] = __float_as_uint(Al[cur][r + 8][kk + tig + 4]);
            }
#pragma unroll
            for (int nt = 0; nt < 4; ++nt) {
                int c = wn + nt * 8 + gid;
                bh_[nt][0] = __float_as_uint(Bh[cur][kk + tig    ][c]);
                bh_[nt][1] = __float_as_uint(Bh[cur][kk + tig + 4][c]);
                bl_[nt][0] = __float_as_uint(Bl[cur][kk + tig    ][c]);
                bl_[nt][1] = __float_as_uint(Bl[cur][kk + tig + 4][c]);
            }
#pragma unroll
            for (int mt = 0; mt < 2; ++mt)
#pragma unroll
                for (int nt = 0; nt < 4; ++nt) {
                    MMA_TF32(acc[mt][nt], ah[mt][0], ah[mt][1], ah[mt][2], ah[mt][3],
                             bl_[nt][0], bl_[nt][1]);
                    MMA_TF32(acc[mt][nt], al[mt][0], al[mt][1], al[mt][2], al[mt][3],
                             bh_[nt][0], bh_[nt][1]);
                    MMA_TF32(acc[mt][nt], ah[mt][0], ah[mt][1], ah[mt][2], ah[mt][3],
                             bh_[nt][0], bh_[nt][1]);
                }
        }
        __syncthreads();
    }

#pragma unroll
    for (int mt = 0; mt < 2; ++mt) {
#pragma unroll
        for (int nt = 0; nt < 4; ++nt) {
            int r0 = m0 + wm + mt * 16 + gid;
            int c  = n0 + wn + nt * 8 + tig * 2;
            float2 v0 = make_float2(acc[mt][nt][0], acc[mt][nt][1]);
            float2 v1 = make_float2(acc[mt][nt][2], acc[mt][nt][3]);
            if (Res != nullptr) {
                float2 r = *reinterpret_cast<const float2*>(Res + (size_t)r0 * N + c);
                v0.x += r.x; v0.y += r.y;
                r = *reinterpret_cast<const float2*>(Res + (size_t)(r0 + 8) * N + c);
                v1.x += r.x; v1.y += r.y;
            }
            *reinterpret_cast<float2*>(C + (size_t)r0 * N + c)       = v0;
            *reinterpret_cast<float2*>(C + (size_t)(r0 + 8) * N + c) = v1;
        }
    }
}

// ---------------------------------------------------------------------------
// RMSNorm (H=512, block=128). split!=0: write hi/lo (feeds GEMM A);
// split==0: write plain fp32 to out (final norm -> d_out).
// ---------------------------------------------------------------------------
__global__ __launch_bounds__(128) void rmsnorm_kernel(
    const float* __restrict__ x, const float* __restrict__ w,
    float* __restrict__ out, float* __restrict__ out_hi,
    float* __restrict__ out_lo, int split)
{
    const int row = blockIdx.x, tid = threadIdx.x;
    float4 v = reinterpret_cast<const float4*>(x + (size_t)row * HDIM)[tid];
    float ss = v.x * v.x + v.y * v.y + v.z * v.z + v.w * v.w;
#pragma unroll
    for (int o = 16; o; o >>= 1) ss += __shfl_xor_sync(0xffffffffu, ss, o);
    __shared__ float sred[4];
    if ((tid & 31) == 0) sred[tid >> 5] = ss;
    __syncthreads();
    float tot = sred[0] + sred[1] + sred[2] + sred[3];
    float inv = rsqrtf(tot * (1.0f / (float)HDIM) + EPSV);
    float4 wv = reinterpret_cast<const float4*>(w)[tid];
    float4 o4 = make_float4(v.x * inv * wv.x, v.y * inv * wv.y,
                            v.z * inv * wv.z, v.w * inv * wv.w);
    if (split) {
        float4 h, l;
        h.x = to_tf32(o4.x); l.x = to_tf32(o4.x - h.x);
        h.y = to_tf32(o4.y); l.y = to_tf32(o4.y - h.y);
        h.z = to_tf32(o4.z); l.z = to_tf32(o4.z - h.z);
        h.w = to_tf32(o4.w); l.w = to_tf32(o4.w - h.w);
        reinterpret_cast<float4*>(out_hi + (size_t)row * HDIM)[tid] = h;
        reinterpret_cast<float4*>(out_lo + (size_t)row * HDIM)[tid] = l;
    } else {
        reinterpret_cast<float4*>(out + (size_t)row * HDIM)[tid] = o4;
    }
}

// ---------------------------------------------------------------------------
// Pack [Wi | Wf | zeros] into hi/lo split form
// ---------------------------------------------------------------------------
__global__ void pack_wif_kernel(const float* __restrict__ Wi,
                                const float* __restrict__ Wf,
                                float* __restrict__ hi, float* __restrict__ lo)
{
    int blk = blockIdx.x;           // l*HDIM + kk
    int col = threadIdx.x;          // 0..63
    float val = 0.0f;
    if (col < NHEAD)            val = Wi[(size_t)blk * NHEAD + col];
    else if (col < 2 * NHEAD)   val = Wf[(size_t)blk * NHEAD + (col - NHEAD)];
    float h = to_tf32(val);
    hi[(size_t)blk * 64 + col] = h;
    lo[(size_t)blk * 64 + col] = to_tf32(val - h);
}

// ---------------------------------------------------------------------------
// mLSTM step (zero state) + per-head RMSNorm + output gate.
// Writes hv split into hi/lo (it is the A-operand of the Wout GEMM).
// ---------------------------------------------------------------------------
__global__ __launch_bounds__(256) void mlstm_kernel(
    const float* __restrict__ q, const float* __restrict__ k,
    const float* __restrict__ v, const float* __restrict__ ogp,
    const float* __restrict__ ifp,           // [NTOK,64]: cols 0..7 = i, 8..15 = f
    const float* __restrict__ bi, const float* __restrict__ bf,
    const float* __restrict__ mhw,           // [NHEAD, DHV]
    float* __restrict__ hv_hi, float* __restrict__ hv_lo)
{
    const int t = blockIdx.x;
    const int h = threadIdx.x >> 5;
    const int lane = threadIdx.x & 31;

    float ip = softcapf(ifp[(size_t)t * 64 + h]      + bi[h]);
    float fp = softcapf(ifp[(size_t)t * 64 + 8 + h]  + bf[h]);
    float flog = logsigf(fp);
    float m = fmaxf(flog, ip);
    float iact = expf(ip - m);

    float qd = q[(size_t)t * QKDIM + h * DHQK + lane];
    float kd = k[(size_t)t * QKDIM + h * DHQK + lane];
    float s = qd * kd;
#pragma unroll
    for (int o = 16; o; o >>= 1) s += __shfl_xor_sync(0xffffffffu, s, o);
    s *= 0.17677669529663687f;  // 32^-0.5

    float qn = iact * s;
    float denom = fmaxf(fabsf(qn), expf(-m)) + EPSV;
    float c = iact * s / denom;

    const int base = t * VDIM + h * DHV;
    float v0 = v[base + lane], v1 = v[base + 32 + lane];
    float h0 = c * v0, h1 = c * v1;

    float ms = h0 * h0 + h1 * h1;
#pragma unroll
    for (int o = 16; o; o >>= 1) ms += __shfl_xor_sync(0xffffffffu, ms, o);
    float inv = rsqrtf(ms * (1.0f / (float)DHV) + EPSV);

    float w0 = mhw[h * DHV + lane],      w1 = mhw[h * DHV + 32 + lane];
    float g0 = sigmoidf_(ogp[base + lane]);
    float g1 = sigmoidf_(ogp[base + 32 + lane]);
    float r0 = h0 * inv * w0 * g0;
    float r1 = h1 * inv * w1 * g1;
    float rh0 = to_tf32(r0), rh1 = to_tf32(r1);
    hv_hi[base + lane]      = rh0;
    hv_lo[base + lane]      = to_tf32(r0 - rh0);
    hv_hi[base + 32 + lane] = rh1;
    hv_lo[base + 32 + lane] = to_tf32(r1 - rh1);
}

// ---------------------------------------------------------------------------
// SwiGLU activation: act = silu(g) * up, written split (feeds W_down GEMM)
// ---------------------------------------------------------------------------
__global__ __launch_bounds__(256) void silu_mul_kernel(
    const float* __restrict__ g, const float* __restrict__ up,
    float* __restrict__ act_hi, float* __restrict__ act_lo, int n4)
{
    int i = blockIdx.x * blockDim.x + threadIdx.x;
    if (i >= n4) return;
    float4 gv = reinterpret_cast<const float4*>(g)[i];
    float4 uv = reinterpret_cast<const float4*>(up)[i];
    float4 a;
    a.x = gv.x * sigmoidf_(gv.x) * uv.x;
    a.y = gv.y * sigmoidf_(gv.y) * uv.y;
    a.z = gv.z * sigmoidf_(gv.z) * uv.z;
    a.w = gv.w * sigmoidf_(gv.w) * uv.w;
    float4 h, l;
    h.x = to_tf32(a.x); l.x = to_tf32(a.x - h.x);
    h.y = to_tf32(a.y); l.y = to_tf32(a.y - h.y);
    h.z = to_tf32(a.z); l.z = to_tf32(a.z - h.z);
    h.w = to_tf32(a.w); l.w = to_tf32(a.w - h.w);
    reinterpret_cast<float4*>(act_hi)[i] = h;
    reinterpret_cast<float4*>(act_lo)[i] = l;
}

// ---------------------------------------------------------------------------
// Host launcher
// ---------------------------------------------------------------------------
static inline float* sym_addr(const void* sym) {
    void* p = nullptr;
    cudaGetSymbolAddress(&p, sym);
    return reinterpret_cast<float*>(p);
}

static inline void gemm_multi(const float* Ahi, const float* Alo,
                              int M, int K, const GemmDesc& d) {
    int nb = d.seg[d.nseg - 1].nstart + d.seg[d.nseg - 1].N / BN;
    dim3 grid(nb, M / BM);
    gemm_presplit_kernel<<<grid, 128>>>(Ahi, Alo, M, K, d);
}

static inline void split_w(const float* in, float* hi, float* lo, size_t n) {
    int n4 = (int)(n / 4);
    split_tf32_kernel<<<(n4 + 255) / 256, 256>>>(in, hi, lo, n4);
}

extern "C" void kernel_launch(void* const* d_in, const int* in_sizes, int n_in,
                              void* d_out, int out_size)
{
    (void)in_sizes; (void)n_in; (void)out_size;
    const float* u       = (const float*)d_in[0];
    const float* norm1_w = (const float*)d_in[1];
    const float* Wq      = (const float*)d_in[2];
    const float* Wk      = (const float*)d_in[3];
    const float* Wv      = (const float*)d_in[4];
    const float* Wi      = (const float*)d_in[5];
    const float* bi      = (const float*)d_in[6];
    const float* Wf      = (const float*)d_in[7];
    const float* bf      = (const float*)d_in[8];
    const float* mh_w    = (const float*)d_in[9];
    const float* Wog     = (const float*)d_in[10];
    const float* Wout    = (const float*)d_in[11];
    const float* norm2_w = (const float*)d_in[12];
    const float* W_up    = (const float*)d_in[13];
    const float* W_gate  = (const float*)d_in[14];
    const float* W_down  = (const float*)d_in[15];
    const float* final_w = (const float*)d_in[16];
    float* out = (float*)d_out;

    float* x    = sym_addr(g_x);
    float* qb   = sym_addr(g_q);
    float* kb   = sym_addr(g_k);
    float* vb   = sym_addr(g_v);
    float* ogb  = sym_addr(g_og);
    float* ifb  = sym_addr(g_if);
    float* gb   = sym_addr(g_gate);
    float* ub   = sym_addr(g_up);
    float* xnh  = sym_addr(g_xn_h),  *xnl  = sym_addr(g_xn_l);
    float* hvh  = sym_addr(g_hv_h),  *hvl  = sym_addr(g_hv_l);
    float* acth = sym_addr(g_act_h), *actl = sym_addr(g_act_l);

    float* wqh = sym_addr(w_q_h),  *wql = sym_addr(w_q_l);
    float* wkh = sym_addr(w_k_h),  *wkl = sym_addr(w_k_l);
    float* wvh = sym_addr(w_v_h),  *wvl = sym_addr(w_v_l);
    float* wogh= sym_addr(w_og_h), *wogl= sym_addr(w_og_l);
    float* woh = sym_addr(w_o_h),  *wol = sym_addr(w_o_l);
    float* wgh = sym_addr(w_g_h),  *wgl = sym_addr(w_g_l);
    float* wuh = sym_addr(w_u_h),  *wul = sym_addr(w_u_l);
    float* wdh = sym_addr(w_d_h),  *wdl = sym_addr(w_d_l);
    float* wifh= sym_addr(w_if_h), *wifl= sym_addr(w_if_l);

    cudaMemcpyAsync(x, u, (size_t)NTOK * HDIM * sizeof(float),
                    cudaMemcpyDeviceToDevice, 0);

    // split all weights once per call
    split_w(Wq,     wqh, wql, (size_t)LAYERS * HDIM * QKDIM);
    split_w(Wk,     wkh, wkl, (size_t)LAYERS * HDIM * QKDIM);
    split_w(Wv,     wvh, wvl, (size_t)LAYERS * HDIM * VDIM);
    split_w(Wog,    wogh, wogl, (size_t)LAYERS * HDIM * VDIM);
    split_w(Wout,   woh, wol, (size_t)LAYERS * VDIM * HDIM);
    split_w(W_gate, wgh, wgl, (size_t)LAYERS * HDIM * FDIM);
    split_w(W_up,   wuh, wul, (size_t)LAYERS * HDIM * FDIM);
    split_w(W_down, wdh, wdl, (size_t)LAYERS * FDIM * HDIM);
    pack_wif_kernel<<<LAYERS * HDIM, 64>>>(Wi, Wf, wifh, wifl);

    for (int l = 0; l < LAYERS; ++l) {
        const size_t oqk = (size_t)l * HDIM * QKDIM;
        const size_t ov  = (size_t)l * HDIM * VDIM;
        const size_t of  = (size_t)l * HDIM * FDIM;
        const size_t oif = (size_t)l * HDIM * 64;

        // --- mLSTM block ---
        rmsnorm_kernel<<<NTOK, 128>>>(x, norm1_w + l * HDIM,
                                      nullptr, xnh, xnl, 1);

        GemmDesc d1;            // q | k | v | og | if
        d1.nseg = 5;
        d1.seg[0] = { wqh + oqk, wql + oqk, qb,  nullptr, QKDIM, 0  };
        d1.seg[1] = { wkh + oqk, wkl + oqk, kb,  nullptr, QKDIM, 4  };
        d1.seg[2] = { wvh + ov,  wvl + ov,  vb,  nullptr, VDIM,  8  };
        d1.seg[3] = { wogh + ov, wogl + ov, ogb, nullptr, VDIM,  16 };
        d1.seg[4] = { wifh + oif, wifl + oif, ifb, nullptr, 64,   24 };
        gemm_multi(xnh, xnl, NTOK, HDIM, d1);

        mlstm_kernel<<<NTOK, 256>>>(qb, kb, vb, ogb, ifb,
                                    bi + l * NHEAD, bf + l * NHEAD,
                                    mh_w + (size_t)l * NHEAD * DHV, hvh, hvl);

        GemmDesc d2;            // x += hv @ Wout
        d2.nseg = 1;
        d2.seg[0] = { woh + ov, wol + ov, x, x, HDIM, 0 };
        gemm_multi(hvh, hvl, NTOK, VDIM, d2);

        // --- FFN block ---
        rmsnorm_kernel<<<NTOK, 128>>>(x, norm2_w + l * HDIM,
                                      nullptr, xnh, xnl, 1);

        GemmDesc d3;            // gate | up
        d3.nseg = 2;
        d3.seg[0] = { wgh + of, wgl + of, gb, nullptr, FDIM, 0  };
        d3.seg[1] = { wuh + of, wul + of, ub, nullptr, FDIM, 22 };
        gemm_multi(xnh, xnl, NTOK, HDIM, d3);

        silu_mul_kernel<<<(NTOK * FDIM / 4 + 255) / 256, 256>>>(
            gb, ub, acth, actl, NTOK * FDIM / 4);

        GemmDesc d4;            // x += act @ W_down
        d4.nseg = 1;
        d4.seg[0] = { wdh + (size_t)l * FDIM * HDIM,
                      wdl + (size_t)l * FDIM * HDIM, x, x, HDIM, 0 };
        gemm_multi(acth, actl, NTOK, FDIM, d4);
    }

    rmsnorm_kernel<<<NTOK, 128>>>(x, final_w, out, nullptr, nullptr, 0);
}

// round 10
// speedup vs baseline: 1.5437x; 1.5437x over previous
#include <cuda_runtime.h>
#include <cuda_bf16.h>
#include <cstdint>

// ---------------------------------------------------------------------------
// Problem constants
// ---------------------------------------------------------------------------
#define LAYERS 4
#define HDIM   512
#define NHEAD  8
#define DHQK   32
#define DHV    64
#define QKDIM  (NHEAD * DHQK)   // 256
#define VDIM   (NHEAD * DHV)    // 512
#define FDIM   1408
#define NTOK   2048              // B*P = 8*256
#define CAPV   15.0f
#define EPSV   1e-6f

typedef __nv_bfloat16  bf16;
typedef __nv_bfloat162 bf162;

// ---------------------------------------------------------------------------
// Device scratch (static: no allocation allowed)
// ---------------------------------------------------------------------------
__device__ float g_x   [NTOK * HDIM];
__device__ float g_q   [NTOK * QKDIM];
__device__ float g_k   [NTOK * QKDIM];
__device__ float g_v   [NTOK * VDIM];
__device__ float g_og  [NTOK * VDIM];
__device__ float g_if  [NTOK * 64];
__device__ float g_gate[NTOK * FDIM];
__device__ float g_up  [NTOK * FDIM];

// bf16 hi/lo split activations (GEMM A-operands, [M][K])
__device__ bf16 g_xn_h [NTOK * HDIM];
__device__ bf16 g_xn_l [NTOK * HDIM];
__device__ bf16 g_hv_h [NTOK * VDIM];
__device__ bf16 g_hv_l [NTOK * VDIM];
__device__ bf16 g_act_h[NTOK * FDIM];
__device__ bf16 g_act_l[NTOK * FDIM];

// bf16 hi/lo split weights, TRANSPOSED to [N][K] (GEMM B-operands)
__device__ bf16 w_q_h [LAYERS * QKDIM * HDIM];
__device__ bf16 w_q_l [LAYERS * QKDIM * HDIM];
__device__ bf16 w_k_h [LAYERS * QKDIM * HDIM];
__device__ bf16 w_k_l [LAYERS * QKDIM * HDIM];
__device__ bf16 w_v_h [LAYERS * VDIM * HDIM];
__device__ bf16 w_v_l [LAYERS * VDIM * HDIM];
__device__ bf16 w_og_h[LAYERS * VDIM * HDIM];
__device__ bf16 w_og_l[LAYERS * VDIM * HDIM];
__device__ bf16 w_o_h [LAYERS * HDIM * VDIM];
__device__ bf16 w_o_l [LAYERS * HDIM * VDIM];
__device__ bf16 w_g_h [LAYERS * FDIM * HDIM];
__device__ bf16 w_g_l [LAYERS * FDIM * HDIM];
__device__ bf16 w_u_h [LAYERS * FDIM * HDIM];
__device__ bf16 w_u_l [LAYERS * FDIM * HDIM];
__device__ bf16 w_d_h [LAYERS * HDIM * FDIM];
__device__ bf16 w_d_l [LAYERS * HDIM * FDIM];
__device__ bf16 w_if_h[LAYERS * 64 * HDIM];
__device__ bf16 w_if_l[LAYERS * 64 * HDIM];

// ---------------------------------------------------------------------------
// Helpers
// ---------------------------------------------------------------------------
__device__ __forceinline__ float softcapf(float x) {
    return CAPV * tanhf(x * (1.0f / CAPV));
}
__device__ __forceinline__ float logsigf(float x) {
    return (x >= 0.0f) ? -log1pf(expf(-x)) : (x - log1pf(expf(x)));
}
__device__ __forceinline__ float sigmoidf_(float x) {
    return 1.0f / (1.0f + expf(-x));
}
__device__ __forceinline__ void cpasync16(uint32_t dst, const void* src) {
    asm volatile("cp.async.cg.shared.global [%0], [%1], 16;\n"
                 :: "r"(dst), "l"(src));
}
__device__ __forceinline__ void split_bf16(float v, bf16& h, bf16& l) {
    h = __float2bfloat16_rn(v);
    l = __float2bfloat16_rn(v - __bfloat162float(h));
}

#define MMA_BF16(acc, a0, a1, a2, a3, b0, b1)                                  \
    asm volatile(                                                              \
        "mma.sync.aligned.m16n8k16.row.col.f32.bf16.bf16.f32 "                 \
        "{%0,%1,%2,%3}, {%4,%5,%6,%7}, {%8,%9}, {%0,%1,%2,%3};\n"              \
        : "+f"(acc[0]), "+f"(acc[1]), "+f"(acc[2]), "+f"(acc[3])               \
        : "r"(a0), "r"(a1), "r"(a2), "r"(a3), "r"(b0), "r"(b1))

// ---------------------------------------------------------------------------
// Weight transform: fp32 W[K][N] (per layer) -> bf16 hi/lo, transposed [N][K].
// Tiled 32x32 transpose, block (32,8), grid (N/32, K/32, LAYERS).
// ---------------------------------------------------------------------------
__global__ __launch_bounds__(256) void split_transpose_kernel(
    const float* __restrict__ in, bf16* __restrict__ hi,
    bf16* __restrict__ lo, int K, int N)
{
    __shared__ float t[32][33];
    const int l = blockIdx.z;
    in += (size_t)l * K * N;
    hi += (size_t)l * N * K;
    lo += (size_t)l * N * K;
    const int n0 = blockIdx.x * 32, k0 = blockIdx.y * 32;
    const int tx = threadIdx.x, ty = threadIdx.y;
#pragma unroll
    for (int j = 0; j < 4; ++j)
        t[ty + 8 * j][tx] = in[(size_t)(k0 + ty + 8 * j) * N + n0 + tx];
    __syncthreads();
#pragma unroll
    for (int j = 0; j < 4; ++j) {
        float v = t[tx][ty + 8 * j];          // (k = k0+tx, n = n0+ty+8j)
        bf16 h, lv; split_bf16(v, h, lv);
        size_t o = (size_t)(n0 + ty + 8 * j) * K + k0 + tx;
        hi[o] = h; lo[o] = lv;
    }
}

// ---------------------------------------------------------------------------
// Pack [Wi | Wf | zeros] -> transposed split [64][HDIM] per layer.
// grid = LAYERS*64 (one n-row each), block 128.
// ---------------------------------------------------------------------------
__global__ void pack_wif_kernel(const float* __restrict__ Wi,
                                const float* __restrict__ Wf,
                                bf16* __restrict__ hi, bf16* __restrict__ lo)
{
    const int l = blockIdx.x >> 6;
    const int n = blockIdx.x & 63;
    for (int k = threadIdx.x; k < HDIM; k += blockDim.x) {
        float val = 0.0f;
        if (n < NHEAD)          val = Wi[((size_t)l * HDIM + k) * NHEAD + n];
        else if (n < 2 * NHEAD) val = Wf[((size_t)l * HDIM + k) * NHEAD + (n - NHEAD)];
        bf16 h, lv; split_bf16(val, h, lv);
        size_t o = ((size_t)l * 64 + n) * HDIM + k;
        hi[o] = h; lo[o] = lv;
    }
}

// ---------------------------------------------------------------------------
// Multi-segment bf16x3 GEMM: C_s[M,N_s] = A[M,K] @ W_s[K,N_s] (+ Res_s)
// A given pre-split bf16 [M][K] (hi,lo); W_s pre-split bf16 TRANSPOSED [N_s][K].
// acc += ah*bl + al*bh + ah*bh  (fp32 accumulate; ~17 effective mantissa bits)
// CTA 64x64x32, 128 threads (4 warps 2x2, warp 32x32), 2-stage cp.async.
// m16n8k16 row.col: A row-major from [M][K]; B col-major from [N][K].
// ---------------------------------------------------------------------------
#define MAXSEG 5
struct GemmSeg {
    const bf16*  Bh;
    const bf16*  Bl;
    float*       C;
    const float* Res;   // nullptr = no residual add
    int          N;
    int          nstart;
};
struct GemmDesc {
    int nseg;
    GemmSeg seg[MAXSEG];
};

#define BM 64
#define BN 64
#define BK 32
#define BKPH 40   // 80B rows: banks (20g+t)%32 distinct -> conflict-free

__global__ __launch_bounds__(128) void gemm_bf16x3_kernel(
    const bf16* __restrict__ Ahi, const bf16* __restrict__ Alo,
    int M, int K, GemmDesc d)
{
    __shared__ bf16 Ah[2][BM][BKPH];   // 10240 B
    __shared__ bf16 Al[2][BM][BKPH];   // 10240 B
    __shared__ bf16 Bh[2][BN][BKPH];   // 10240 B   ([n][k] layout)
    __shared__ bf16 Bl[2][BN][BKPH];   // 10240 B   => 40960 B total

    // --- segment lookup (uniform per CTA) ---
    const int nblk = blockIdx.x;
    int si = 0;
#pragma unroll
    for (int t = 1; t < MAXSEG; ++t)
        if (t < d.nseg && nblk >= d.seg[t].nstart) si = t;
    const bf16* __restrict__ SBh = d.seg[si].Bh;
    const bf16* __restrict__ SBl = d.seg[si].Bl;
    float*      __restrict__ C   = d.seg[si].C;
    const float* __restrict__ Res = d.seg[si].Res;
    const int N  = d.seg[si].N;
    const int n0 = (nblk - d.seg[si].nstart) * BN;
    const int m0 = blockIdx.y * BM;

    const int tid  = threadIdx.x;
    const int warp = tid >> 5;
    const int lane = tid & 31;
    const int wm   = (warp >> 1) * 32;
    const int wn   = (warp & 1) * 32;
    const int gid  = lane >> 2;          // 0..7
    const int tig  = lane & 3;           // 0..3

    // tile staging: each tile is 64 rows x 64B (32 bf16), 80B pitch in smem.
    // 256 16B-chunks per tile -> 2 chunks/thread; x4 tiles (Ah,Al,Bh,Bl).
    int rrow[2], rc16[2];
    uint32_t ah_dst[2][2], al_dst[2][2], bh_dst[2][2], bl_dst[2][2];
#pragma unroll
    for (int it = 0; it < 2; ++it) {
        int idx = tid + it * 128;
        rrow[it] = idx >> 2;          // 0..63
        rc16[it] = idx & 3;           // 16B chunk within row
#pragma unroll
        for (int s = 0; s < 2; ++s) {
            ah_dst[s][it] = (uint32_t)__cvta_generic_to_shared(&Ah[s][rrow[it]][rc16[it] * 8]);
            al_dst[s][it] = (uint32_t)__cvta_generic_to_shared(&Al[s][rrow[it]][rc16[it] * 8]);
            bh_dst[s][it] = (uint32_t)__cvta_generic_to_shared(&Bh[s][rrow[it]][rc16[it] * 8]);
            bl_dst[s][it] = (uint32_t)__cvta_generic_to_shared(&Bl[s][rrow[it]][rc16[it] * 8]);
        }
    }

    float acc[2][4][4];
#pragma unroll
    for (int mt = 0; mt < 2; ++mt)
#pragma unroll
        for (int nt = 0; nt < 4; ++nt)
#pragma unroll
            for (int r = 0; r < 4; ++r) acc[mt][nt][r] = 0.0f;

    const int nk = K / BK;

#pragma unroll
    for (int it = 0; it < 2; ++it) {
        cpasync16(ah_dst[0][it], Ahi + (size_t)(m0 + rrow[it]) * K + rc16[it] * 8);
        cpasync16(al_dst[0][it], Alo + (size_t)(m0 + rrow[it]) * K + rc16[it] * 8);
        cpasync16(bh_dst[0][it], SBh + (size_t)(n0 + rrow[it]) * K + rc16[it] * 8);
        cpasync16(bl_dst[0][it], SBl + (size_t)(n0 + rrow[it]) * K + rc16[it] * 8);
    }
    asm volatile("cp.async.commit_group;\n");

    for (int kt = 0; kt < nk; ++kt) {
        const int cur = kt & 1;
        if (kt + 1 < nk) {
            const int nxt = cur ^ 1;
            const int koff = (kt + 1) * BK;
#pragma unroll
            for (int it = 0; it < 2; ++it) {
                cpasync16(ah_dst[nxt][it], Ahi + (size_t)(m0 + rrow[it]) * K + koff + rc16[it] * 8);
                cpasync16(al_dst[nxt][it], Alo + (size_t)(m0 + rrow[it]) * K + koff + rc16[it] * 8);
                cpasync16(bh_dst[nxt][it], SBh + (size_t)(n0 + rrow[it]) * K + koff + rc16[it] * 8);
                cpasync16(bl_dst[nxt][it], SBl + (size_t)(n0 + rrow[it]) * K + koff + rc16[it] * 8);
            }
            asm volatile("cp.async.commit_group;\n");
            asm volatile("cp.async.wait_group 1;\n");
        } else {
            asm volatile("cp.async.wait_group 0;\n");
        }
        __syncthreads();

#pragma unroll
        for (int kk = 0; kk < BK; kk += 16) {
            // a-frag m16n8k16: a0=(r, 2tig..+1) a1=(r+8,..) a2=(r, 2tig+8..+9) a3=(r+8,..)
            uint32_t ah[2][4], al[2][4], bh_[4][2], bl_[4][2];
#pragma unroll
            for (int mt = 0; mt < 2; ++mt) {
                int r = wm + mt * 16 + gid;
                ah[mt][0] = *(const uint32_t*)&Ah[cur][r    ][kk + 2 * tig];
                ah[mt][1] = *(const uint32_t*)&Ah[cur][r + 8][kk + 2 * tig];
                ah[mt][2] = *(const uint32_t*)&Ah[cur][r    ][kk + 2 * tig + 8];
                ah[mt][3] = *(const uint32_t*)&Ah[cur][r + 8][kk + 2 * tig + 8];
                al[mt][0] = *(const uint32_t*)&Al[cur][r    ][kk + 2 * tig];
                al[mt][1] = *(const uint32_t*)&Al[cur][r + 8][kk + 2 * tig];
                al[mt][2] = *(const uint32_t*)&Al[cur][r    ][kk + 2 * tig + 8];
                al[mt][3] = *(const uint32_t*)&Al[cur][r + 8][kk + 2 * tig + 8];
            }
            // b-frag: b0=(k 2tig..+1, n c), b1=(k 2tig+8..+9, n c); smem is [n][k]
#pragma unroll
            for (int nt = 0; nt < 4; ++nt) {
                int c = wn + nt * 8 + gid;
                bh_[nt][0] = *(const uint32_t*)&Bh[cur][c][kk + 2 * tig];
                bh_[nt][1] = *(const uint32_t*)&Bh[cur][c][kk + 2 * tig + 8];
                bl_[nt][0] = *(const uint32_t*)&Bl[cur][c][kk + 2 * tig];
                bl_[nt][1] = *(const uint32_t*)&Bl[cur][c][kk + 2 * tig + 8];
            }
#pragma unroll
            for (int mt = 0; mt < 2; ++mt)
#pragma unroll
                for (int nt = 0; nt < 4; ++nt) {
                    MMA_BF16(acc[mt][nt], ah[mt][0], ah[mt][1], ah[mt][2], ah[mt][3],
                             bl_[nt][0], bl_[nt][1]);
                    MMA_BF16(acc[mt][nt], al[mt][0], al[mt][1], al[mt][2], al[mt][3],
                             bh_[nt][0], bh_[nt][1]);
                    MMA_BF16(acc[mt][nt], ah[mt][0], ah[mt][1], ah[mt][2], ah[mt][3],
                             bh_[nt][0], bh_[nt][1]);
                }
        }
        __syncthreads();
    }

#pragma unroll
    for (int mt = 0; mt < 2; ++mt) {
#pragma unroll
        for (int nt = 0; nt < 4; ++nt) {
            int r0 = m0 + wm + mt * 16 + gid;
            int c  = n0 + wn + nt * 8 + tig * 2;
            float2 v0 = make_float2(acc[mt][nt][0], acc[mt][nt][1]);
            float2 v1 = make_float2(acc[mt][nt][2], acc[mt][nt][3]);
            if (Res != nullptr) {
                float2 r = *reinterpret_cast<const float2*>(Res + (size_t)r0 * N + c);
                v0.x += r.x; v0.y += r.y;
                r = *reinterpret_cast<const float2*>(Res + (size_t)(r0 + 8) * N + c);
                v1.x += r.x; v1.y += r.y;
            }
            *reinterpret_cast<float2*>(C + (size_t)r0 * N + c)       = v0;
            *reinterpret_cast<float2*>(C + (size_t)(r0 + 8) * N + c) = v1;
        }
    }
}

// ---------------------------------------------------------------------------
// RMSNorm (H=512, block=128). split!=0: write bf16 hi/lo (feeds GEMM A);
// split==0: write plain fp32 (final norm -> d_out).
// ---------------------------------------------------------------------------
__global__ __launch_bounds__(128) void rmsnorm_kernel(
    const float* __restrict__ x, const float* __restrict__ w,
    float* __restrict__ out, bf16* __restrict__ out_hi,
    bf16* __restrict__ out_lo, int split)
{
    const int row = blockIdx.x, tid = threadIdx.x;
    float4 v = reinterpret_cast<const float4*>(x + (size_t)row * HDIM)[tid];
    float ss = v.x * v.x + v.y * v.y + v.z * v.z + v.w * v.w;
#pragma unroll
    for (int o = 16; o; o >>= 1) ss += __shfl_xor_sync(0xffffffffu, ss, o);
    __shared__ float sred[4];
    if ((tid & 31) == 0) sred[tid >> 5] = ss;
    __syncthreads();
    float tot = sred[0] + sred[1] + sred[2] + sred[3];
    float inv = rsqrtf(tot * (1.0f / (float)HDIM) + EPSV);
    float4 wv = reinterpret_cast<const float4*>(w)[tid];
    float4 o4 = make_float4(v.x * inv * wv.x, v.y * inv * wv.y,
                            v.z * inv * wv.z, v.w * inv * wv.w);
    if (split) {
        bf16 hx, lx, hy, ly, hz, lz, hw, lw;
        split_bf16(o4.x, hx, lx); split_bf16(o4.y, hy, ly);
        split_bf16(o4.z, hz, lz); split_bf16(o4.w, hw, lw);
        bf162* oh = reinterpret_cast<bf162*>(out_hi + (size_t)row * HDIM);
        bf162* ol = reinterpret_cast<bf162*>(out_lo + (size_t)row * HDIM);
        oh[tid * 2]     = __halves2bfloat162(hx, hy);
        oh[tid * 2 + 1] = __halves2bfloat162(hz, hw);
        ol[tid * 2]     = __halves2bfloat162(lx, ly);
        ol[tid * 2 + 1] = __halves2bfloat162(lz, lw);
    } else {
        reinterpret_cast<float4*>(out + (size_t)row * HDIM)[tid] = o4;
    }
}

// ---------------------------------------------------------------------------
// mLSTM step (zero state) + per-head RMSNorm + output gate.
// Writes hv split bf16 hi/lo (A-operand of the Wout GEMM).
// ---------------------------------------------------------------------------
__global__ __launch_bounds__(256) void mlstm_kernel(
    const float* __restrict__ q, const float* __restrict__ k,
    const float* __restrict__ v, const float* __restrict__ ogp,
    const float* __restrict__ ifp,           // [NTOK,64]: cols 0..7 = i, 8..15 = f
    const float* __restrict__ bi, const float* __restrict__ bf,
    const float* __restrict__ mhw,           // [NHEAD, DHV]
    bf16* __restrict__ hv_hi, bf16* __restrict__ hv_lo)
{
    const int t = blockIdx.x;
    const int h = threadIdx.x >> 5;
    const int lane = threadIdx.x & 31;

    float ip = softcapf(ifp[(size_t)t * 64 + h]      + bi[h]);
    float fp = softcapf(ifp[(size_t)t * 64 + 8 + h]  + bf[h]);
    float flog = logsigf(fp);
    float m = fmaxf(flog, ip);
    float iact = expf(ip - m);

    float qd = q[(size_t)t * QKDIM + h * DHQK + lane];
    float kd = k[(size_t)t * QKDIM + h * DHQK + lane];
    float s = qd * kd;
#pragma unroll
    for (int o = 16; o; o >>= 1) s += __shfl_xor_sync(0xffffffffu, s, o);
    s *= 0.17677669529663687f;  // 32^-0.5

    float qn = iact * s;
    float denom = fmaxf(fabsf(qn), expf(-m)) + EPSV;
    float c = iact * s / denom;

    const int base = t * VDIM + h * DHV;
    float v0 = v[base + lane], v1 = v[base + 32 + lane];
    float h0 = c * v0, h1 = c * v1;

    float ms = h0 * h0 + h1 * h1;
#pragma unroll
    for (int o = 16; o; o >>= 1) ms += __shfl_xor_sync(0xffffffffu, ms, o);
    float inv = rsqrtf(ms * (1.0f / (float)DHV) + EPSV);

    float w0 = mhw[h * DHV + lane],      w1 = mhw[h * DHV + 32 + lane];
    float g0 = sigmoidf_(ogp[base + lane]);
    float g1 = sigmoidf_(ogp[base + 32 + lane]);
    float r0 = h0 * inv * w0 * g0;
    float r1 = h1 * inv * w1 * g1;
    bf16 rh, rl;
    split_bf16(r0, rh, rl);
    hv_hi[base + lane] = rh;           hv_lo[base + lane] = rl;
    split_bf16(r1, rh, rl);
    hv_hi[base + 32 + lane] = rh;      hv_lo[base + 32 + lane] = rl;
}

// ---------------------------------------------------------------------------
// SwiGLU: act = silu(g) * up, written split bf16 (feeds W_down GEMM)
// ---------------------------------------------------------------------------
__global__ __launch_bounds__(256) void silu_mul_kernel(
    const float* __restrict__ g, const float* __restrict__ up,
    bf16* __restrict__ act_hi, bf16* __restrict__ act_lo, int n4)
{
    int i = blockIdx.x * blockDim.x + threadIdx.x;
    if (i >= n4) return;
    float4 gv = reinterpret_cast<const float4*>(g)[i];
    float4 uv = reinterpret_cast<const float4*>(up)[i];
    float4 a;
    a.x = gv.x * sigmoidf_(gv.x) * uv.x;
    a.y = gv.y * sigmoidf_(gv.y) * uv.y;
    a.z = gv.z * sigmoidf_(gv.z) * uv.z;
    a.w = gv.w * sigmoidf_(gv.w) * uv.w;
    bf16 hx, lx, hy, ly, hz, lz, hw, lw;
    split_bf16(a.x, hx, lx); split_bf16(a.y, hy, ly);
    split_bf16(a.z, hz, lz); split_bf16(a.w, hw, lw);
    bf162* oh = reinterpret_cast<bf162*>(act_hi);
    bf162* ol = reinterpret_cast<bf162*>(act_lo);
    oh[i * 2]     = __halves2bfloat162(hx, hy);
    oh[i * 2 + 1] = __halves2bfloat162(hz, hw);
    ol[i * 2]     = __halves2bfloat162(lx, ly);
    ol[i * 2 + 1] = __halves2bfloat162(lz, lw);
}

// ---------------------------------------------------------------------------
// Host launcher
// ---------------------------------------------------------------------------
static inline void* sym_addr_v(const void* sym) {
    void* p = nullptr;
    cudaGetSymbolAddress(&p, sym);
    return p;
}
#define SYMF(s)  ((float*)sym_addr_v(s))
#define SYMB(s)  ((bf16*)sym_addr_v(s))

static inline void gemm_multi(const bf16* Ahi, const bf16* Alo,
                              int M, int K, const GemmDesc& d) {
    int nb = d.seg[d.nseg - 1].nstart + d.seg[d.nseg - 1].N / BN;
    dim3 grid(nb, M / BM);
    gemm_bf16x3_kernel<<<grid, 128>>>(Ahi, Alo, M, K, d);
}

static inline void split_tr(const float* in, bf16* hi, bf16* lo, int K, int N) {
    dim3 grid(N / 32, K / 32, LAYERS);
    split_transpose_kernel<<<grid, dim3(32, 8)>>>(in, hi, lo, K, N);
}

extern "C" void kernel_launch(void* const* d_in, const int* in_sizes, int n_in,
                              void* d_out, int out_size)
{
    (void)in_sizes; (void)n_in; (void)out_size;
    const float* u       = (const float*)d_in[0];
    const float* norm1_w = (const float*)d_in[1];
    const float* Wq      = (const float*)d_in[2];
    const float* Wk      = (const float*)d_in[3];
    const float* Wv      = (const float*)d_in[4];
    const float* Wi      = (const float*)d_in[5];
    const float* bi      = (const float*)d_in[6];
    const float* Wf      = (const float*)d_in[7];
    const float* bf_     = (const float*)d_in[8];
    const float* mh_w    = (const float*)d_in[9];
    const float* Wog     = (const float*)d_in[10];
    const float* Wout    = (const float*)d_in[11];
    const float* norm2_w = (const float*)d_in[12];
    const float* W_up    = (const float*)d_in[13];
    const float* W_gate  = (const float*)d_in[14];
    const float* W_down  = (const float*)d_in[15];
    const float* final_w = (const float*)d_in[16];
    float* out = (float*)d_out;

    float* x   = SYMF(g_x);
    float* qb  = SYMF(g_q);
    float* kb  = SYMF(g_k);
    float* vb  = SYMF(g_v);
    float* ogb = SYMF(g_og);
    float* ifb = SYMF(g_if);
    float* gb  = SYMF(g_gate);
    float* ub  = SYMF(g_up);
    bf16* xnh  = SYMB(g_xn_h),  *xnl  = SYMB(g_xn_l);
    bf16* hvh  = SYMB(g_hv_h),  *hvl  = SYMB(g_hv_l);
    bf16* acth = SYMB(g_act_h), *actl = SYMB(g_act_l);

    bf16* wqh = SYMB(w_q_h),  *wql = SYMB(w_q_l);
    bf16* wkh = SYMB(w_k_h),  *wkl = SYMB(w_k_l);
    bf16* wvh = SYMB(w_v_h),  *wvl = SYMB(w_v_l);
    bf16* wogh= SYMB(w_og_h), *wogl= SYMB(w_og_l);
    bf16* woh = SYMB(w_o_h),  *wol = SYMB(w_o_l);
    bf16* wgh = SYMB(w_g_h),  *wgl = SYMB(w_g_l);
    bf16* wuh = SYMB(w_u_h),  *wul = SYMB(w_u_l);
    bf16* wdh = SYMB(w_d_h),  *wdl = SYMB(w_d_l);
    bf16* wifh= SYMB(w_if_h), *wifl= SYMB(w_if_l);

    cudaMemcpyAsync(x, u, (size_t)NTOK * HDIM * sizeof(float),
                    cudaMemcpyDeviceToDevice, 0);

    // weight transforms: fp32 [K][N] -> bf16 hi/lo [N][K], once per call
    split_tr(Wq,     wqh,  wql,  HDIM, QKDIM);
    split_tr(Wk,     wkh,  wkl,  HDIM, QKDIM);
    split_tr(Wv,     wvh,  wvl,  HDIM, VDIM);
    split_tr(Wog,    wogh, wogl, HDIM, VDIM);
    split_tr(Wout,   woh,  wol,  VDIM, HDIM);
    split_tr(W_gate, wgh,  wgl,  HDIM, FDIM);
    split_tr(W_up,   wuh,  wul,  HDIM, FDIM);
    split_tr(W_down, wdh,  wdl,  FDIM, HDIM);
    pack_wif_kernel<<<LAYERS * 64, 128>>>(Wi, Wf, wifh, wifl);

    for (int l = 0; l < LAYERS; ++l) {
        const size_t oqk = (size_t)l * QKDIM * HDIM;
        const size_t ov  = (size_t)l * VDIM * HDIM;
        const size_t of  = (size_t)l * FDIM * HDIM;
        const size_t oif = (size_t)l * 64 * HDIM;

        // --- mLSTM block ---
        rmsnorm_kernel<<<NTOK, 128>>>(x, norm1_w + l * HDIM,
                                      nullptr, xnh, xnl, 1);

        GemmDesc d1;            // q | k | v | og | if
        d1.nseg = 5;
        d1.seg[0] = { wqh + oqk,  wql + oqk,  qb,  nullptr, QKDIM, 0  };
        d1.seg[1] = { wkh + oqk,  wkl + oqk,  kb,  nullptr, QKDIM, 4  };
        d1.seg[2] = { wvh + ov,   wvl + ov,   vb,  nullptr, VDIM,  8  };
        d1.seg[3] = { wogh + ov,  wogl + ov,  ogb, nullptr, VDIM,  16 };
        d1.seg[4] = { wifh + oif, wifl + oif, ifb, nullptr, 64,    24 };
        gemm_multi(xnh, xnl, NTOK, HDIM, d1);

        mlstm_kernel<<<NTOK, 256>>>(qb, kb, vb, ogb, ifb,
                                    bi + l * NHEAD, bf_ + l * NHEAD,
                                    mh_w + (size_t)l * NHEAD * DHV, hvh, hvl);

        GemmDesc d2;            // x += hv @ Wout
        d2.nseg = 1;
        d2.seg[0] = { woh + ov, wol + ov, x, x, HDIM, 0 };
        gemm_multi(hvh, hvl, NTOK, VDIM, d2);

        // --- FFN block ---
        rmsnorm_kernel<<<NTOK, 128>>>(x, norm2_w + l * HDIM,
                                      nullptr, xnh, xnl, 1);

        GemmDesc d3;            // gate | up
        d3.nseg = 2;
        d3.seg[0] = { wgh + of, wgl + of, gb, nullptr, FDIM, 0  };
        d3.seg[1] = { wuh + of, wul + of, ub, nullptr, FDIM, 22 };
        gemm_multi(xnh, xnl, NTOK, HDIM, d3);

        silu_mul_kernel<<<(NTOK * FDIM / 4 + 255) / 256, 256>>>(
            gb, ub, acth, actl, NTOK * FDIM / 4);

        GemmDesc d4;            // x += act @ W_down
        d4.nseg = 1;
        d4.seg[0] = { wdh + (size_t)l * HDIM * FDIM,
                      wdl + (size_t)l * HDIM * FDIM, x, x, HDIM, 0 };
        gemm_multi(acth, actl, NTOK, FDIM, d4);
    }

    rmsnorm_kernel<<<NTOK, 128>>>(x, final_w, out, nullptr, nullptr, 0);
}